// round 1
// baseline (speedup 1.0000x reference)
#include <cuda_runtime.h>
#include <cstdint>
#include <math_constants.h>

// Problem constants
#define BB 64
#define SS 512
#define HH 768
#define LL 9

// Scratch (no allocations allowed)
__device__ float g_em[BB * SS * LL];   // emissions [B,S,L]
__device__ float g_num[BB];            // numerator per batch
__device__ float g_loss[BB];           // denom - num per batch

__device__ __forceinline__ float ex2f(float x) {
    float y;
    asm("ex2.approx.ftz.f32 %0, %1;" : "=f"(y) : "f"(x));
    return y;
}
__device__ __forceinline__ float lg2f(float x) {
    float y;
    asm("lg2.approx.ftz.f32 %0, %1;" : "=f"(y) : "f"(x));
    return y;
}

// ---------------------------------------------------------------------------
// Kernel 1: emissions = hs @ W + b
// 4 rows per warp, 8 warps per block -> 32 rows/block, 1024 blocks.
// W transposed into shared [9][768] so lanes do conflict-free LDS.128.
// ---------------------------------------------------------------------------
__global__ __launch_bounds__(256) void emis_kernel(
    const float* __restrict__ hs, const float* __restrict__ W,
    const float* __restrict__ bias)
{
    __shared__ float shW[LL][HH];   // transposed W
    __shared__ float shb[LL];

    int tid = threadIdx.x;
    for (int idx = tid; idx < LL * HH; idx += 256) {
        int l = idx / HH, h = idx - l * HH;
        shW[l][h] = W[h * LL + l];
    }
    if (tid < LL) shb[tid] = bias[tid];
    __syncthreads();

    int w = tid >> 5, lane = tid & 31;
    int row0 = (blockIdx.x * 8 + w) * 4;            // 4 consecutive rows
    const float4* hs4 = (const float4*)hs;          // 192 float4 per row

    float acc[4][LL];
#pragma unroll
    for (int r = 0; r < 4; r++)
#pragma unroll
        for (int l = 0; l < LL; l++) acc[r][l] = 0.f;

#pragma unroll
    for (int k = 0; k < 6; k++) {
        int c = lane + 32 * k;
        float4 x[4];
#pragma unroll
        for (int r = 0; r < 4; r++) x[r] = hs4[(size_t)(row0 + r) * 192 + c];
#pragma unroll
        for (int l = 0; l < LL; l++) {
            float4 wv = ((const float4*)shW[l])[c];
#pragma unroll
            for (int r = 0; r < 4; r++) {
                acc[r][l] += x[r].x * wv.x + x[r].y * wv.y +
                             x[r].z * wv.z + x[r].w * wv.w;
            }
        }
    }

    // cross-lane butterfly reductions (all 36 sums)
#pragma unroll
    for (int r = 0; r < 4; r++)
#pragma unroll
        for (int l = 0; l < LL; l++) {
            float v = acc[r][l];
            v += __shfl_xor_sync(0xffffffffu, v, 16);
            v += __shfl_xor_sync(0xffffffffu, v, 8);
            v += __shfl_xor_sync(0xffffffffu, v, 4);
            v += __shfl_xor_sync(0xffffffffu, v, 2);
            v += __shfl_xor_sync(0xffffffffu, v, 1);
            acc[r][l] = v;
        }

#pragma unroll
    for (int r = 0; r < 4; r++) {
        if (lane == r) {
#pragma unroll
            for (int l = 0; l < LL; l++)
                g_em[(size_t)(row0 + r) * LL + l] = acc[r][l] + shb[l];
        }
    }
}

// ---------------------------------------------------------------------------
// Kernel 2: numerator per batch (gold-path score). One block per batch.
// ---------------------------------------------------------------------------
__global__ __launch_bounds__(256) void crf_num_kernel(
    const int* __restrict__ mask, const int* __restrict__ labels,
    const float* __restrict__ trans, const float* __restrict__ start_t,
    const float* __restrict__ end_t)
{
    int b = blockIdx.x;
    int t = threadIdx.x;
    __shared__ float red[256];
    __shared__ int redi[256];

    const float* emb = g_em + (size_t)b * SS * LL;
    const int* lb = labels + b * SS;
    const int* mb = mask + b * SS;

    float acc = 0.f;
    int msum = 0;
    for (int s = t; s < SS; s += 256) {
        int l = lb[s];
        int m = mb[s];
        msum += m;
        float et = emb[s * LL + l];
        if (s == 0) {
            acc += start_t[l] + et;            // unmasked first term
        } else {
            acc += m ? (trans[lb[s - 1] * LL + l] + et) : 0.f;
        }
    }
    red[t] = acc;
    redi[t] = msum;
    __syncthreads();
    for (int off = 128; off > 0; off >>= 1) {
        if (t < off) { red[t] += red[t + off]; redi[t] += redi[t + off]; }
        __syncthreads();
    }
    if (t == 0) {
        int last = redi[0] - 1;
        g_num[b] = red[0] + end_t[lb[last]];
    }
}

// ---------------------------------------------------------------------------
// Kernel 3: CRF forward scan (log-partition). One warp per batch.
// Lane j owns column j; all math in log2 domain.
// ---------------------------------------------------------------------------
__global__ __launch_bounds__(32) void crf_scan_kernel(
    const int* __restrict__ mask, const float* __restrict__ trans,
    const float* __restrict__ start_t, const float* __restrict__ end_t)
{
    const float L2E = 1.4426950408889634f;   // log2(e)
    const float LN2 = 0.6931471805599453f;

    int b = blockIdx.x;
    int j = threadIdx.x;
    bool act = (j < LL);

    float tcol[LL];
#pragma unroll
    for (int i = 0; i < LL; i++)
        tcol[i] = act ? trans[i * LL + j] * L2E : 0.f;

    const float* emb = g_em + (size_t)b * SS * LL;
    const int* mb = mask + b * SS;

    float alpha = act ? (start_t[j] + emb[j]) * L2E : -CUDART_INF_F;

    // 2-deep register prefetch of emissions and mask
    float e1 = act ? emb[1 * LL + j] : 0.f;
    int   m1 = mb[1];
    float e2 = act ? emb[2 * LL + j] : 0.f;
    int   m2 = mb[2];

    for (int s = 1; s < SS; s++) {
        float ecur = e1; int mcur = m1;
        e1 = e2; m1 = m2;
        if (s + 2 < SS) {
            e2 = act ? emb[(s + 2) * LL + j] : 0.f;
            m2 = mb[s + 2];
        }

        float v[LL];
#pragma unroll
        for (int i = 0; i < LL; i++)
            v[i] = __shfl_sync(0xffffffffu, alpha, i) + tcol[i];

        // max (pairwise tree, in-register)
        float mx = fmaxf(fmaxf(fmaxf(v[0], v[1]), fmaxf(v[2], v[3])),
                         fmaxf(fmaxf(v[4], v[5]), fmaxf(v[6], v[7])));
        mx = fmaxf(mx, v[8]);

        float ssum = 0.f;
#pragma unroll
        for (int i = 0; i < LL; i++) ssum += ex2f(v[i] - mx);

        float nxt = mx + lg2f(ssum) + ecur * L2E;
        alpha = (mcur && act) ? nxt : alpha;
    }

    // denom = ln-sum-exp over states of alpha + end_trans
    float vv = act ? alpha + end_t[j] * L2E : -CUDART_INF_F;
    float mm = vv;
#pragma unroll
    for (int i = 0; i < LL; i++)
        mm = fmaxf(mm, __shfl_sync(0xffffffffu, vv, i));
    float e = act ? ex2f(vv - mm) : 0.f;
    float ssum = 0.f;
#pragma unroll
    for (int i = 0; i < LL; i++)
        ssum += __shfl_sync(0xffffffffu, e, i);

    if (j == 0) {
        float denom = (mm + lg2f(ssum)) * LN2;
        g_loss[b] = denom - g_num[b];
    }
}

// ---------------------------------------------------------------------------
// Kernel 4: deterministic final reduction of 64 per-batch losses
// ---------------------------------------------------------------------------
__global__ __launch_bounds__(64) void finalize_kernel(float* out)
{
    __shared__ float s[64];
    int t = threadIdx.x;
    s[t] = g_loss[t];
    __syncthreads();
    for (int off = 32; off > 0; off >>= 1) {
        if (t < off) s[t] += s[t + off];
        __syncthreads();
    }
    if (t == 0) out[0] = s[0];
}

// ---------------------------------------------------------------------------
extern "C" void kernel_launch(void* const* d_in, const int* in_sizes, int n_in,
                              void* d_out, int out_size)
{
    const float* hs      = (const float*)d_in[0];   // hidden_states [B,S,H]
    const int*   mask    = (const int*)  d_in[1];   // attention_mask [B,S]
    const int*   labels  = (const int*)  d_in[2];   // labels [B,S]
    const float* W       = (const float*)d_in[3];   // [H,L]
    const float* bias    = (const float*)d_in[4];   // [L]
    const float* start_t = (const float*)d_in[5];   // [L]
    const float* end_t   = (const float*)d_in[6];   // [L]
    const float* trans   = (const float*)d_in[7];   // [L,L]
    float* out = (float*)d_out;

    emis_kernel<<<1024, 256>>>(hs, W, bias);
    crf_num_kernel<<<BB, 256>>>(mask, labels, trans, start_t, end_t);
    crf_scan_kernel<<<BB, 32>>>(mask, trans, start_t, end_t);
    finalize_kernel<<<1, 64>>>(out);
}

// round 2
// speedup vs baseline: 2.3036x; 2.3036x over previous
#include <cuda_runtime.h>
#include <cstdint>
#include <math_constants.h>

#define BB 64
#define SS 512
#define HH 768
#define LL 9
#define NC 16          // chunks per batch
#define CLEN 32        // steps per chunk

// Scratch (no allocations allowed)
__device__ float g_em[BB * SS * LL];      // raw emissions [B,S,L]
__device__ float g_expem[BB * SS * LL];   // exp(emissions)
__device__ float g_num[BB];               // numerator per batch
__device__ float g_P[BB * NC * 81];       // chunk transfer matrices (linear domain)
__device__ float g_rs[BB * NC * LL];      // per-row log2 scales of chunk matrices

__device__ __forceinline__ float ex2f(float x) {
    float y; asm("ex2.approx.ftz.f32 %0, %1;" : "=f"(y) : "f"(x)); return y;
}
__device__ __forceinline__ float lg2f(float x) {
    float y; asm("lg2.approx.ftz.f32 %0, %1;" : "=f"(y) : "f"(x)); return y;
}

#define L2E 1.4426950408889634f
#define LN2 0.6931471805599453f

// ---------------------------------------------------------------------------
// Kernel 1: emissions = hs @ W + b ; also writes exp(emissions).
// 4 rows per warp, 8 warps/block, 1024 blocks.
// ---------------------------------------------------------------------------
__global__ __launch_bounds__(256) void emis_kernel(
    const float* __restrict__ hs, const float* __restrict__ W,
    const float* __restrict__ bias)
{
    __shared__ float shW[LL][HH];
    __shared__ float shb[LL];

    int tid = threadIdx.x;
    for (int idx = tid; idx < LL * HH; idx += 256) {
        int l = idx / HH, h = idx - l * HH;
        shW[l][h] = W[h * LL + l];
    }
    if (tid < LL) shb[tid] = bias[tid];
    __syncthreads();

    int w = tid >> 5, lane = tid & 31;
    int row0 = (blockIdx.x * 8 + w) * 4;
    const float4* hs4 = (const float4*)hs;

    float acc[4][LL];
#pragma unroll
    for (int r = 0; r < 4; r++)
#pragma unroll
        for (int l = 0; l < LL; l++) acc[r][l] = 0.f;

#pragma unroll
    for (int k = 0; k < 6; k++) {
        int c = lane + 32 * k;
        float4 x[4];
#pragma unroll
        for (int r = 0; r < 4; r++) x[r] = hs4[(size_t)(row0 + r) * 192 + c];
#pragma unroll
        for (int l = 0; l < LL; l++) {
            float4 wv = ((const float4*)shW[l])[c];
#pragma unroll
            for (int r = 0; r < 4; r++) {
                acc[r][l] += x[r].x * wv.x + x[r].y * wv.y +
                             x[r].z * wv.z + x[r].w * wv.w;
            }
        }
    }

#pragma unroll
    for (int r = 0; r < 4; r++)
#pragma unroll
        for (int l = 0; l < LL; l++) {
            float v = acc[r][l];
            v += __shfl_xor_sync(0xffffffffu, v, 16);
            v += __shfl_xor_sync(0xffffffffu, v, 8);
            v += __shfl_xor_sync(0xffffffffu, v, 4);
            v += __shfl_xor_sync(0xffffffffu, v, 2);
            v += __shfl_xor_sync(0xffffffffu, v, 1);
            acc[r][l] = v;
        }

#pragma unroll
    for (int r = 0; r < 4; r++) {
        if (lane == r) {
#pragma unroll
            for (int l = 0; l < LL; l++) {
                float e = acc[r][l] + shb[l];
                size_t o = (size_t)(row0 + r) * LL + l;
                g_em[o] = e;
                g_expem[o] = ex2f(e * L2E);
            }
        }
    }
}

// ---------------------------------------------------------------------------
// Kernel 2: numerator per batch (gold-path score). One block per batch.
// ---------------------------------------------------------------------------
__global__ __launch_bounds__(256) void crf_num_kernel(
    const int* __restrict__ mask, const int* __restrict__ labels,
    const float* __restrict__ trans, const float* __restrict__ start_t,
    const float* __restrict__ end_t)
{
    int b = blockIdx.x;
    int t = threadIdx.x;
    __shared__ float red[256];
    __shared__ int redi[256];

    const float* emb = g_em + (size_t)b * SS * LL;
    const int* lb = labels + b * SS;
    const int* mb = mask + b * SS;

    float acc = 0.f;
    int msum = 0;
    for (int s = t; s < SS; s += 256) {
        int l = lb[s];
        int m = mb[s];
        msum += m;
        float et = emb[s * LL + l];
        if (s == 0) acc += start_t[l] + et;
        else        acc += m ? (trans[lb[s - 1] * LL + l] + et) : 0.f;
    }
    red[t] = acc;
    redi[t] = msum;
    __syncthreads();
    for (int off = 128; off > 0; off >>= 1) {
        if (t < off) { red[t] += red[t + off]; redi[t] += redi[t + off]; }
        __syncthreads();
    }
    if (t == 0) {
        int last = redi[0] - 1;
        g_num[b] = red[0] + end_t[lb[last]];
    }
}

// ---------------------------------------------------------------------------
// Kernel 3: chunked scan — each block computes the 9x9 linear-domain transfer
// matrix of a 32-step chunk. Grid (NC, BB), 96 threads (3 warps x 3 rows).
// Lane layout within warp: lr = lane/9 (row-in-warp), j = lane%9 (column).
// Row = warp*3 + lr. Rescale every 8 steps; per-row log2 scale in g_rs.
// ---------------------------------------------------------------------------
__global__ __launch_bounds__(96) void crf_chunk_kernel(
    const int* __restrict__ mask, const float* __restrict__ trans)
{
    __shared__ float sem[CLEN * LL];
    __shared__ int smk[CLEN];

    int c = blockIdx.x;
    int b = blockIdx.y;
    int tid = threadIdx.x;
    int warp = tid >> 5, lane = tid & 31;
    int lr = lane / 9, j = lane - lr * 9;   // j in 0..8 (garbage-safe for idle lanes)
    int row = warp * 3 + lr;
    int t0 = c * CLEN;

    // stage chunk's exp-emissions + mask into smem (coalesced)
    for (int i = tid; i < CLEN * LL; i += 96)
        sem[i] = g_expem[((size_t)b * SS + t0) * LL + i];
    if (tid < CLEN) smk[tid] = mask[b * SS + t0 + tid];

    // per-lane column of exp(trans)
    float et[LL];
#pragma unroll
    for (int i = 0; i < LL; i++)
        et[i] = ex2f(trans[i * LL + j] * L2E);

    __syncthreads();

    int base = lr * 9;                  // shfl source base for this row group
    float a = (row == j) ? 1.f : 0.f;   // identity init
    float rs = 0.f;                     // log2 row scale

    int s0 = (c == 0) ? 1 : 0;          // chunk 0 starts at t=1 (t=0 is alpha0)
#pragma unroll 8
    for (int s = s0; s < CLEN; s++) {
        float em = sem[s * LL + j];
        int   m  = smk[s];
        float v0 = 0.f, v1 = 0.f, v2 = 0.f;
#pragma unroll
        for (int i = 0; i < 9; i += 3) {
            v0 += __shfl_sync(0xffffffffu, a, base + i)     * et[i];
            v1 += __shfl_sync(0xffffffffu, a, base + i + 1) * et[i + 1];
            v2 += __shfl_sync(0xffffffffu, a, base + i + 2) * et[i + 2];
        }
        float v = (v0 + v1 + v2) * em;
        a = m ? v : a;

        if ((s & 7) == 7) {             // rescale by row max
            float mx = -CUDART_INF_F;
#pragma unroll
            for (int i = 0; i < 9; i++)
                mx = fmaxf(mx, __shfl_sync(0xffffffffu, a, base + i));
            float inv = 1.f / mx;
            a *= inv;
            rs += lg2f(mx);
        }
    }

    if (warp < 3 && lane < 27) {
        size_t mo = ((size_t)b * NC + c) * 81 + row * 9 + j;
        g_P[mo] = a;
        if (j == 0) g_rs[((size_t)b * NC + c) * LL + row] = rs;
    }
}

// ---------------------------------------------------------------------------
// Kernel 4: combine chunk matrices per batch + denom + final sum. One block,
// 704 threads = 22 warps; warp w handles batches 3w..3w+2 (9 lanes each).
// ---------------------------------------------------------------------------
__global__ __launch_bounds__(704) void crf_combine_kernel(
    const float* __restrict__ start_t, const float* __restrict__ end_t,
    float* __restrict__ out)
{
    __shared__ float sloss[BB];

    int tid = threadIdx.x;
    int warp = tid >> 5, lane = tid & 31;
    int lr = lane / 9, j = lane - lr * 9;
    int batch = warp * 3 + lr;
    bool act = (lane < 27) && (batch < BB);
    int bb = act ? batch : 0;           // clamp for safe loads
    int base = lr * 9;

    // alpha0 (linear) = exp(start) * exp(em[0])
    float alpha = ex2f(start_t[j] * L2E) * g_expem[(size_t)bb * SS * LL + j];
    float sc = 0.f;

    for (int c = 0; c < NC; c++) {
        size_t pb = ((size_t)bb * NC + c);
        float p[LL];
#pragma unroll
        for (int i = 0; i < LL; i++) p[i] = g_P[pb * 81 + i * 9 + j];
        float rj = g_rs[pb * LL + j];

        float rmax = -CUDART_INF_F;
#pragma unroll
        for (int i = 0; i < LL; i++)
            rmax = fmaxf(rmax, __shfl_sync(0xffffffffu, rj, base + i));

        float v = 0.f;
#pragma unroll
        for (int i = 0; i < LL; i++) {
            float ai = __shfl_sync(0xffffffffu, alpha, base + i);
            float ri = __shfl_sync(0xffffffffu, rj,    base + i);
            v += ai * ex2f(ri - rmax) * p[i];
        }

        float mx = -CUDART_INF_F;
#pragma unroll
        for (int i = 0; i < LL; i++)
            mx = fmaxf(mx, __shfl_sync(0xffffffffu, v, base + i));
        alpha = v * (1.f / mx);
        sc += rmax + lg2f(mx);
    }

    // denom = log( sum_j alpha_j * exp(end_j) ) + sc  (log2 domain -> ln)
    float s1 = alpha * ex2f(end_t[j] * L2E);
    float ssum = 0.f;
#pragma unroll
    for (int i = 0; i < LL; i++)
        ssum += __shfl_sync(0xffffffffu, s1, base + i);

    if (act && j == 0) {
        float denom = (sc + lg2f(ssum)) * LN2;
        sloss[batch] = denom - g_num[batch];
    }
    __syncthreads();

    if (tid < 32) {
        float v = sloss[tid] + sloss[tid + 32];
        v += __shfl_xor_sync(0xffffffffu, v, 16);
        v += __shfl_xor_sync(0xffffffffu, v, 8);
        v += __shfl_xor_sync(0xffffffffu, v, 4);
        v += __shfl_xor_sync(0xffffffffu, v, 2);
        v += __shfl_xor_sync(0xffffffffu, v, 1);
        if (tid == 0) out[0] = v;
    }
}

// ---------------------------------------------------------------------------
extern "C" void kernel_launch(void* const* d_in, const int* in_sizes, int n_in,
                              void* d_out, int out_size)
{
    const float* hs      = (const float*)d_in[0];
    const int*   mask    = (const int*)  d_in[1];
    const int*   labels  = (const int*)  d_in[2];
    const float* W       = (const float*)d_in[3];
    const float* bias    = (const float*)d_in[4];
    const float* start_t = (const float*)d_in[5];
    const float* end_t   = (const float*)d_in[6];
    const float* trans   = (const float*)d_in[7];
    float* out = (float*)d_out;

    emis_kernel<<<1024, 256>>>(hs, W, bias);
    crf_num_kernel<<<BB, 256>>>(mask, labels, trans, start_t, end_t);
    crf_chunk_kernel<<<dim3(NC, BB), 96>>>(mask, trans);
    crf_combine_kernel<<<1, 704>>>(start_t, end_t, out);
}